// round 2
// baseline (speedup 1.0000x reference)
#include <cuda_runtime.h>

#define NN 50000
#define EE 600000
#define LN_EPS 1e-5f

typedef unsigned long long ull;

// ---- scratch (device globals; no allocations allowed) ----
__device__ float g_msg[(size_t)NN * 128];   // per-node FiLM message
__device__ float g_h[(size_t)NN * 128];     // layernormed aggregated features
__device__ int   g_rowptr[NN + 1];
__device__ int   g_counts[NN];
__device__ int   g_cursor[NN];
__device__ int   g_srclist[EE];

// ---- packed f32x2 helpers (B300: FFMA2 doubles fp32 throughput) ----
__device__ __forceinline__ ull ffma2(ull a, ull b, ull c) {
    ull d;
    asm("fma.rn.f32x2 %0, %1, %2, %3;" : "=l"(d) : "l"(a), "l"(b), "l"(c));
    return d;
}
__device__ __forceinline__ ull pack2(float x) {
    ull d;
    asm("mov.b64 %0, {%1, %1};" : "=l"(d) : "f"(x));
    return d;
}
__device__ __forceinline__ float2 unpack2(ull v) {
    float2 r;
    asm("mov.b64 {%0, %1}, %2;" : "=f"(r.x), "=f"(r.y) : "l"(v));
    return r;
}

// ============================ CSR build ============================

__global__ void k_zero(int n) {
    int i = blockIdx.x * blockDim.x + threadIdx.x;
    if (i < n) { g_counts[i] = 0; g_cursor[i] = 0; }
}

__global__ void k_count(const int* __restrict__ dst, int e) {
    int i = blockIdx.x * blockDim.x + threadIdx.x;
    if (i < e) atomicAdd(&g_counts[dst[i]], 1);
}

__global__ void k_scan(int n, int e) {
    __shared__ int part[1024];
    int tid = threadIdx.x;
    int per = (n + 1023) >> 10;
    int base = tid * per;
    int s = 0;
    for (int i = 0; i < per; i++) {
        int idx = base + i;
        if (idx < n) s += g_counts[idx];
    }
    part[tid] = s;
    __syncthreads();
    for (int off = 1; off < 1024; off <<= 1) {
        int add = (tid >= off) ? part[tid - off] : 0;
        __syncthreads();
        part[tid] += add;
        __syncthreads();
    }
    int run = (tid == 0) ? 0 : part[tid - 1];
    for (int i = 0; i < per; i++) {
        int idx = base + i;
        if (idx < n) { g_rowptr[idx] = run; run += g_counts[idx]; }
    }
    if (tid == 1023) g_rowptr[n] = e;
}

__global__ void k_fill(const int* __restrict__ src, const int* __restrict__ dst, int e) {
    int i = blockIdx.x * blockDim.x + threadIdx.x;
    if (i < e) {
        int d = dst[i];
        int slot = g_rowptr[d] + atomicAdd(&g_cursor[d], 1);
        g_srclist[slot] = src[i];
    }
}

// ============================ FiLM GEMM ============================
// msg[n][j] = relu( (x.F1[j]) * (x.W[j]) + (x.F1[128+j]) ),  j in [0,128)
// 256 threads, 64-node tile. Weights (3x128x128) k-major in smem (192KB) + x tile (32KB).
// warp = 8 nodes; lane = cols 4l..4l+3 as two f32x2 pairs; f32x2 packs K-pairs.

#define SMEM_FILM ((3 * 128 * 128 + 64 * 128) * 4)

__global__ void __launch_bounds__(256, 1)
k_film_gemm(const float* __restrict__ Xext, int use_internal,
            const float* __restrict__ W, const float* __restrict__ F, int n) {
    extern __shared__ float sm[];
    float* sW = sm;                    // [3][128 k][128 j]
    float* sX = sm + 3 * 128 * 128;    // [64][128]
    const float* X = use_internal ? g_h : Xext;

    int t = threadIdx.x;
    int nbase = blockIdx.x * 64;
    int nt = n - nbase; if (nt > 64) nt = 64;

    // ---- load weights, transposed to k-major ----
    {
        int j = t & 127, half = t >> 7;
        #pragma unroll
        for (int m = 0; m < 3; m++) {
            const float4* srcp = (m == 0) ? (const float4*)(W + (size_t)j * 128)
                                          : (const float4*)(F + (size_t)((m - 1) * 128 + j) * 128);
            #pragma unroll
            for (int kk = 0; kk < 16; kk++) {
                int q = kk * 2 + half;   // float4 index 0..31 along k
                float4 v = srcp[q];
                int k = q * 4;
                float* dp = sW + ((m * 128 + k) * 128 + j);
                dp[0 * 128] = v.x; dp[1 * 128] = v.y; dp[2 * 128] = v.z; dp[3 * 128] = v.w;
            }
        }
    }
    // ---- load x tile (coalesced) ----
    {
        const float4* x4 = (const float4*)X;
        float4* sx4 = (float4*)sX;
        #pragma unroll
        for (int i = 0; i < 8; i++) {
            int idx = t + i * 256;           // 0..2047
            int row = idx >> 5, q = idx & 31;
            float4 v = (row < nt) ? x4[(size_t)(nbase + row) * 32 + q]
                                  : make_float4(0.f, 0.f, 0.f, 0.f);
            sx4[row * 32 + q] = v;
        }
    }
    __syncthreads();

    int warp = t >> 5, lane = t & 31;
    int n0 = warp * 8;
    const float* sXb = sX + n0 * 128;

    ull accW[8][2], accG[8][2], accB[8][2];
    #pragma unroll
    for (int i = 0; i < 8; i++) {
        accW[i][0] = 0ull; accW[i][1] = 0ull;
        accG[i][0] = 0ull; accG[i][1] = 0ull;
        accB[i][0] = 0ull; accB[i][1] = 0ull;
    }

    const float* sW0 = sW + 4 * lane;
    const float* sW1 = sW + 128 * 128 + 4 * lane;
    const float* sW2 = sW + 2 * 128 * 128 + 4 * lane;

    #pragma unroll 4
    for (int k = 0; k < 128; k++) {
        ull xp[8];
        #pragma unroll
        for (int i = 0; i < 8; i++) xp[i] = pack2(sXb[i * 128 + k]);
        ulonglong2 w0 = *(const ulonglong2*)(sW0 + k * 128);
        ulonglong2 w1 = *(const ulonglong2*)(sW1 + k * 128);
        ulonglong2 w2 = *(const ulonglong2*)(sW2 + k * 128);
        #pragma unroll
        for (int i = 0; i < 8; i++) {
            accW[i][0] = ffma2(xp[i], w0.x, accW[i][0]);
            accW[i][1] = ffma2(xp[i], w0.y, accW[i][1]);
            accG[i][0] = ffma2(xp[i], w1.x, accG[i][0]);
            accG[i][1] = ffma2(xp[i], w1.y, accG[i][1]);
            accB[i][0] = ffma2(xp[i], w2.x, accB[i][0]);
            accB[i][1] = ffma2(xp[i], w2.y, accB[i][1]);
        }
    }

    // epilogue: msg = relu(gamma * m + beta); each f32x2 acc holds 2 K-partials summed by unpack-add
    #pragma unroll
    for (int i = 0; i < 8; i++) {
        if (n0 + i < nt) {
            int node = nbase + n0 + i;
            float2 mA = unpack2(accW[i][0]), mB = unpack2(accW[i][1]);
            float2 gA = unpack2(accG[i][0]), gB = unpack2(accG[i][1]);
            float2 bA = unpack2(accB[i][0]), bB = unpack2(accB[i][1]);
            // NOTE: f32x2 here packs K-pairs, so lo/hi are partial sums over even/odd k.
            // Wait—no: we packed (k,k+1) into one reg, so lo accumulates even-k, hi odd-k.
            // Actually lo/hi each accumulate a disjoint half of K; the full dot is lo+hi.
            float m0 = mA.x + mA.y;  // hmm — see packing below
            (void)m0;
            // Correct combination: each acc[i][p] lo half used k's low float, hi half k's high float.
            // But pack2(x) put the SAME x in both halves, and w0.x held (w[k][c0], w[k][c1]):
            // => lo = sum_k x[k]*w[k][c0], hi = sum_k x[k]*w[k][c1]. Two separate columns. No add needed.
            float4 o;
            o.x = fmaxf(fmaf(gA.x, mA.x, bA.x), 0.f);
            o.y = fmaxf(fmaf(gA.y, mA.y, bA.y), 0.f);
            o.z = fmaxf(fmaf(gB.x, mB.x, bB.x), 0.f);
            o.w = fmaxf(fmaf(gB.y, mB.y, bB.y), 0.f);
            *(float4*)(g_msg + (size_t)node * 128 + 4 * lane) = o;
        }
    }
}

// ===================== gather (segment sum) + layernorm =====================
// one warp per destination node; lane covers 4 contiguous floats.

__global__ void __launch_bounds__(256)
k_gather_ln(const float* __restrict__ gw, const float* __restrict__ bw, int n) {
    int node = blockIdx.x * 8 + (threadIdx.x >> 5);
    int lane = threadIdx.x & 31;
    if (node >= n) return;
    int beg = g_rowptr[node], end = g_rowptr[node + 1];
    const float4* msg4 = (const float4*)g_msg;
    float4 a = make_float4(0.f, 0.f, 0.f, 0.f);
    for (int i = beg; i < end; i += 32) {
        int cnt = end - i; if (cnt > 32) cnt = 32;
        int s = (lane < cnt) ? g_srclist[i + lane] : 0;
        for (int j = 0; j < cnt; j++) {
            int ss = __shfl_sync(0xffffffffu, s, j);
            float4 v = __ldg(&msg4[(size_t)ss * 32 + lane]);
            a.x += v.x; a.y += v.y; a.z += v.z; a.w += v.w;
        }
    }
    float loc = a.x + a.y + a.z + a.w;
    #pragma unroll
    for (int o = 16; o; o >>= 1) loc += __shfl_xor_sync(0xffffffffu, loc, o);
    float mu = loc * (1.0f / 128.0f);
    float d0 = a.x - mu, d1 = a.y - mu, d2 = a.z - mu, d3 = a.w - mu;
    float l2 = d0 * d0 + d1 * d1 + d2 * d2 + d3 * d3;
    #pragma unroll
    for (int o = 16; o; o >>= 1) l2 += __shfl_xor_sync(0xffffffffu, l2, o);
    float rs = rsqrtf(l2 * (1.0f / 128.0f) + LN_EPS);
    float4 gg = __ldg(&((const float4*)gw)[lane]);
    float4 bb = __ldg(&((const float4*)bw)[lane]);
    float4 o4;
    o4.x = d0 * rs * gg.x + bb.x;
    o4.y = d1 * rs * gg.y + bb.y;
    o4.z = d2 * rs * gg.z + bb.z;
    o4.w = d3 * rs * gg.w + bb.w;
    ((float4*)g_h)[(size_t)node * 32 + lane] = o4;
}

// ===================== projection: sigmoid(h @ Wp.T + bp) =====================

#define SMEM_PROJ ((128 * 64 + 64 * 128) * 4)

__global__ void __launch_bounds__(256, 1)
k_proj(const float* __restrict__ Wp, const float* __restrict__ bp,
       float* __restrict__ out, int n) {
    extern __shared__ float sm[];
    float* sWp = sm;               // [128 k][64 j]
    float* sX = sm + 128 * 64;     // [64][128]
    int t = threadIdx.x;
    int nbase = blockIdx.x * 64;
    int nt = n - nbase; if (nt > 64) nt = 64;

    {
        int j = t & 63, seg = t >> 6;   // 4 segs along k
        const float4* w4 = (const float4*)(Wp + (size_t)j * 128);
        #pragma unroll
        for (int kk = 0; kk < 8; kk++) {
            int q = seg * 8 + kk;       // float4 index 0..31
            float4 v = w4[q];
            int k = q * 4;
            sWp[(k + 0) * 64 + j] = v.x;
            sWp[(k + 1) * 64 + j] = v.y;
            sWp[(k + 2) * 64 + j] = v.z;
            sWp[(k + 3) * 64 + j] = v.w;
        }
    }
    {
        const float4* x4 = (const float4*)g_h;
        float4* sx4 = (float4*)sX;
        #pragma unroll
        for (int i = 0; i < 8; i++) {
            int idx = t + i * 256;
            int row = idx >> 5, q = idx & 31;
            float4 v = (row < nt) ? x4[(size_t)(nbase + row) * 32 + q]
                                  : make_float4(0.f, 0.f, 0.f, 0.f);
            sx4[row * 32 + q] = v;
        }
    }
    __syncthreads();

    int warp = t >> 5, lane = t & 31;
    int n0 = warp * 8;
    const float* sXb = sX + n0 * 128;
    ull acc[8];
    #pragma unroll
    for (int i = 0; i < 8; i++) acc[i] = 0ull;

    #pragma unroll 4
    for (int k = 0; k < 128; k++) {
        ull wv = *(const ull*)(sWp + k * 64 + 2 * lane);
        #pragma unroll
        for (int i = 0; i < 8; i++)
            acc[i] = ffma2(pack2(sXb[i * 128 + k]), wv, acc[i]);
    }

    float2 bv = ((const float2*)bp)[lane];
    #pragma unroll
    for (int i = 0; i < 8; i++) {
        if (n0 + i < nt) {
            float2 s = unpack2(acc[i]);
            float v0 = 1.0f / (1.0f + __expf(-(s.x + bv.x)));
            float v1 = 1.0f / (1.0f + __expf(-(s.y + bv.y)));
            *(float2*)(out + (size_t)(nbase + n0 + i) * 64 + 2 * lane) = make_float2(v0, v1);
        }
    }
}

// ============================ launch ============================

extern "C" void kernel_launch(void* const* d_in, const int* in_sizes, int n_in,
                              void* d_out, int out_size) {
    const float* feats = (const float*)d_in[0];
    const int*   src   = (const int*)d_in[1];
    const int*   dst   = (const int*)d_in[2];
    const float* W1    = (const float*)d_in[3];
    const float* F1    = (const float*)d_in[4];
    const float* g1    = (const float*)d_in[5];
    const float* b1    = (const float*)d_in[6];
    const float* W2    = (const float*)d_in[7];
    const float* F2    = (const float*)d_in[8];
    const float* g2    = (const float*)d_in[9];
    const float* b2    = (const float*)d_in[10];
    const float* Wp    = (const float*)d_in[11];
    const float* bp    = (const float*)d_in[12];
    float* out = (float*)d_out;

    int n = in_sizes[0] / 128;   // 50000
    int e = in_sizes[1];         // 600000

    cudaFuncSetAttribute(k_film_gemm, cudaFuncAttributeMaxDynamicSharedMemorySize, SMEM_FILM);
    cudaFuncSetAttribute(k_proj, cudaFuncAttributeMaxDynamicSharedMemorySize, SMEM_PROJ);

    int tiles = (n + 63) / 64;

    // CSR build (int atomics only; avoids 76.8M float RED ops per layer)
    k_zero<<<(n + 255) / 256, 256>>>(n);
    k_count<<<(e + 255) / 256, 256>>>(dst, e);
    k_scan<<<1, 1024>>>(n, e);
    k_fill<<<(e + 255) / 256, 256>>>(src, dst, e);

    // layer 1
    k_film_gemm<<<tiles, 256, SMEM_FILM>>>(feats, 0, W1, F1, n);
    k_gather_ln<<<(n + 7) / 8, 256>>>(g1, b1, n);
    // layer 2
    k_film_gemm<<<tiles, 256, SMEM_FILM>>>(nullptr, 1, W2, F2, n);
    k_gather_ln<<<(n + 7) / 8, 256>>>(g2, b2, n);
    // projection
    k_proj<<<tiles, 256, SMEM_PROJ>>>(Wp, bp, out, n);
}

// round 10
// speedup vs baseline: 1.7501x; 1.7501x over previous
#include <cuda_runtime.h>
#include <cuda_bf16.h>

#define NN 50000
#define EE 600000
#define LN_EPS 1e-5f

typedef unsigned long long ull;
typedef unsigned int u32;

// ---- scratch (device globals; no allocations allowed) ----
__device__ float g_msg[(size_t)NN * 128];
__device__ float g_h[(size_t)NN * 128];
__device__ int   g_rowptr[NN + 1];
__device__ int   g_counts[NN];
__device__ int   g_cursor[NN];
__device__ int   g_srclist[EE];
// row-major bf16 hi/lo weights: [layer][matrix 0..2][hi/lo][128*128]
__device__ __align__(16) __nv_bfloat16 g_wprep[2][3][2][16384];

// ============================ helpers ============================

__device__ __forceinline__ u32 smem_u32(const void* p) {
    u32 a;
    asm("{ .reg .u64 t; cvta.to.shared.u64 t, %1; cvt.u32.u64 %0, t; }" : "=r"(a) : "l"(p));
    return a;
}
__device__ __forceinline__ void ldsm_x4(u32& r0, u32& r1, u32& r2, u32& r3, u32 addr) {
    asm volatile("ldmatrix.sync.aligned.m8n8.x4.shared.b16 {%0,%1,%2,%3}, [%4];"
                 : "=r"(r0), "=r"(r1), "=r"(r2), "=r"(r3) : "r"(addr));
}
__device__ __forceinline__ void mma16816(float* d, const u32* a, u32 b0, u32 b1) {
    asm volatile(
        "mma.sync.aligned.m16n8k16.row.col.f32.bf16.bf16.f32 "
        "{%0,%1,%2,%3}, {%4,%5,%6,%7}, {%8,%9}, {%0,%1,%2,%3};"
        : "+f"(d[0]), "+f"(d[1]), "+f"(d[2]), "+f"(d[3])
        : "r"(a[0]), "r"(a[1]), "r"(a[2]), "r"(a[3]), "r"(b0), "r"(b1));
}

// ---- packed f32x2 helpers (proj kernel) ----
__device__ __forceinline__ ull ffma2(ull a, ull b, ull c) {
    ull d;
    asm("fma.rn.f32x2 %0, %1, %2, %3;" : "=l"(d) : "l"(a), "l"(b), "l"(c));
    return d;
}
__device__ __forceinline__ ull pack2(float x) {
    ull d;
    asm("mov.b64 %0, {%1, %1};" : "=l"(d) : "f"(x));
    return d;
}
__device__ __forceinline__ float2 unpack2(ull v) {
    float2 r;
    asm("mov.b64 {%0, %1}, %2;" : "=f"(r.x), "=f"(r.y) : "l"(v));
    return r;
}

// ============================ CSR build ============================

__global__ void k_zero(int n) {
    int i = blockIdx.x * blockDim.x + threadIdx.x;
    if (i < n) { g_counts[i] = 0; g_cursor[i] = 0; }
}
__global__ void k_count(const int* __restrict__ dst, int e) {
    int i = blockIdx.x * blockDim.x + threadIdx.x;
    if (i < e) atomicAdd(&g_counts[dst[i]], 1);
}
__global__ void k_scan(int n, int e) {
    __shared__ int part[1024];
    int tid = threadIdx.x;
    int per = (n + 1023) >> 10;
    int base = tid * per;
    int s = 0;
    for (int i = 0; i < per; i++) { int idx = base + i; if (idx < n) s += g_counts[idx]; }
    part[tid] = s;
    __syncthreads();
    for (int off = 1; off < 1024; off <<= 1) {
        int add = (tid >= off) ? part[tid - off] : 0;
        __syncthreads();
        part[tid] += add;
        __syncthreads();
    }
    int run = (tid == 0) ? 0 : part[tid - 1];
    for (int i = 0; i < per; i++) {
        int idx = base + i;
        if (idx < n) { g_rowptr[idx] = run; run += g_counts[idx]; }
    }
    if (tid == 1023) g_rowptr[n] = e;
}
__global__ void k_fill(const int* __restrict__ src, const int* __restrict__ dst, int e) {
    int i = blockIdx.x * blockDim.x + threadIdx.x;
    if (i < e) {
        int d = dst[i];
        int slot = g_rowptr[d] + atomicAdd(&g_cursor[d], 1);
        g_srclist[slot] = src[i];
    }
}

// ==================== weight prep: fp32 -> row-major bf16 hi/lo ====================

__global__ void k_prep(const float* __restrict__ W1, const float* __restrict__ F1,
                       const float* __restrict__ W2, const float* __restrict__ F2) {
    int b = blockIdx.x;           // 0..5
    int layer = b / 3, m = b % 3;
    const float* src;
    if (layer == 0) src = (m == 0) ? W1 : (F1 + (m - 1) * 16384);
    else            src = (m == 0) ? W2 : (F2 + (m - 1) * 16384);
    __nv_bfloat16* dhi = &g_wprep[layer][m][0][0];
    __nv_bfloat16* dlo = &g_wprep[layer][m][1][0];
    for (int i = threadIdx.x; i < 16384; i += blockDim.x) {
        float v = src[i];
        __nv_bfloat16 h = __float2bfloat16(v);
        __nv_bfloat16 l = __float2bfloat16(v - __bfloat162float(h));
        dhi[i] = h;
        dlo[i] = l;
    }
}

// ============================ FiLM GEMM (mma.sync bf16) ============================
// CTA: 128 nodes x 384 outputs, 8 warps, each warp 16 rows x 128 cols.
// D = Ah*Bh + Al*Bh + Ah*Bl per matrix. First matrix (m) stashed to smem fp32;
// gamma/beta kept in regs. Epilogue: msg = relu(gamma*m + beta).

// smem layout (bytes)
#define SA_HI 0
#define SA_LO 32768
#define SB_HI 65536
#define SB_LO 98304
#define SD0   131072
#define D0_PITCH 132
#define SMEM_MMA (131072 + 128 * D0_PITCH * 4)   // 198656

// chunk swizzle: 16B chunks, pitch 256B (16 chunks/row)
__device__ __forceinline__ u32 sw_addr(u32 base, int row, int chunk) {
    return base + (u32)row * 256u + (u32)((chunk ^ (row & 7)) << 4);
}

// stage one 128x128 bf16 matrix (32KB) from global row-major into swizzled smem
__device__ __forceinline__ void stage32k(u32 sdst, const __nv_bfloat16* src, int tid) {
    const uint4* s4 = (const uint4*)src;
    #pragma unroll
    for (int it = 0; it < 8; it++) {
        int idx = tid + it * 256;          // 0..2047 chunks
        int row = idx >> 4, c = idx & 15;
        uint4 v = __ldg(&s4[idx]);
        *(uint4*)(u32)0;  // placeholder avoided
        asm volatile("st.shared.v4.b32 [%0], {%1,%2,%3,%4};"
                     :: "r"(sw_addr(sdst, row, c)), "r"(v.x), "r"(v.y), "r"(v.z), "r"(v.w));
    }
}

// compute one 128x128 matrix product into acc[16][4]
__device__ __forceinline__ void gemm_mat(float acc[16][4], u32 sAhi, u32 sAlo,
                                         u32 sBhi, u32 sBlo, int w, int lane) {
    // per-thread ldmatrix geometry
    int tile = lane >> 3;                 // 0..3
    int rA = 16 * w + (tile & 1) * 8 + (lane & 7);
    int rAs = rA & 7;
    int hiA = tile >> 1;                  // chunk +0/+1
    u32 aHiRow = sAhi + (u32)rA * 256u;
    u32 aLoRow = sAlo + (u32)rA * 256u;
    int rB = (tile & 1) * 8 + (lane & 7); // row within 16-row B block
    int rBs = rB & 7;
    int hiB = tile >> 1;

    #pragma unroll
    for (int kt = 0; kt < 8; kt++) {
        u32 ah[4], al[4];
        u32 aoff = (u32)(((kt * 2 + hiA) ^ rAs) << 4);
        ldsm_x4(ah[0], ah[1], ah[2], ah[3], aHiRow + aoff);
        ldsm_x4(al[0], al[1], al[2], al[3], aLoRow + aoff);
        #pragma unroll
        for (int nt2 = 0; nt2 < 8; nt2++) {
            int rowB = nt2 * 16 + rB;
            u32 boff = (u32)rowB * 256u + (u32)(((kt * 2 + hiB) ^ rBs) << 4);
            u32 bh[4], bl[4];
            ldsm_x4(bh[0], bh[1], bh[2], bh[3], sBhi + boff);
            ldsm_x4(bl[0], bl[1], bl[2], bl[3], sBlo + boff);
            // even n-tile: frags {q0,q2}; odd: {q1,q3}
            mma16816(acc[2 * nt2 + 0], ah, bh[0], bh[2]);
            mma16816(acc[2 * nt2 + 0], al, bh[0], bh[2]);
            mma16816(acc[2 * nt2 + 0], ah, bl[0], bl[2]);
            mma16816(acc[2 * nt2 + 1], ah, bh[1], bh[3]);
            mma16816(acc[2 * nt2 + 1], al, bh[1], bh[3]);
            mma16816(acc[2 * nt2 + 1], ah, bl[1], bl[3]);
        }
    }
}

__global__ void __launch_bounds__(256, 1)
k_film_mma(const float* __restrict__ Xext, int use_internal, int layer, int n) {
    extern __shared__ char sm[];
    u32 sb = smem_u32(sm);
    float* sD0 = (float*)(sm + SD0);
    int tid = threadIdx.x, w = tid >> 5, lane = tid & 31;
    const float* X = use_internal ? g_h : Xext;
    int nbase = blockIdx.x * 128;
    int ntail = n - nbase; if (ntail > 128) ntail = 128;

    // zero A smem only for the tail tile
    if (ntail < 128) {
        #pragma unroll
        for (int i = 0; i < 16; i++) {
            asm volatile("st.shared.v4.b32 [%0], {%1,%1,%1,%1};"
                         :: "r"(sb + SA_HI + (u32)(tid * 16 + i * 4096)), "r"(0u));
        }
    }
    __syncthreads();

    // ---- convert X tile to bf16 hi/lo, swizzled ----
    #pragma unroll
    for (int it = 0; it < 8; it++) {
        int idx = tid + it * 256;          // 2048 chunks
        int row = idx >> 4, c = idx & 15;
        if (row < ntail) {
            const float* xp = X + (size_t)(nbase + row) * 128 + c * 8;
            float4 v0 = *(const float4*)xp;
            float4 v1 = *(const float4*)(xp + 4);
            float f[8] = {v0.x, v0.y, v0.z, v0.w, v1.x, v1.y, v1.z, v1.w};
            u32 hp[4], lp[4];
            #pragma unroll
            for (int q = 0; q < 4; q++) {
                __nv_bfloat16 h0 = __float2bfloat16(f[2 * q]);
                __nv_bfloat16 h1 = __float2bfloat16(f[2 * q + 1]);
                __nv_bfloat16 l0 = __float2bfloat16(f[2 * q] - __bfloat162float(h0));
                __nv_bfloat16 l1 = __float2bfloat16(f[2 * q + 1] - __bfloat162float(h1));
                __nv_bfloat162 hh; hh.x = h0; hh.y = h1;
                __nv_bfloat162 ll; ll.x = l0; ll.y = l1;
                hp[q] = *(u32*)&hh;
                lp[q] = *(u32*)&ll;
            }
            asm volatile("st.shared.v4.b32 [%0], {%1,%2,%3,%4};"
                         :: "r"(sw_addr(sb + SA_HI, row, c)), "r"(hp[0]), "r"(hp[1]), "r"(hp[2]), "r"(hp[3]));
            asm volatile("st.shared.v4.b32 [%0], {%1,%2,%3,%4};"
                         :: "r"(sw_addr(sb + SA_LO, row, c)), "r"(lp[0]), "r"(lp[1]), "r"(lp[2]), "r"(lp[3]));
        }
    }

    const __nv_bfloat16* prep = &g_wprep[layer][0][0][0];
    int r0 = 16 * w + (lane >> 2);
    int c0 = 2 * (lane & 3);

    // ---- matrix 0 (W -> m), stash to smem fp32 ----
    {
        stage32k(sb + SB_HI, prep, tid);
        stage32k(sb + SB_LO, prep + 16384, tid);
        __syncthreads();
        float acc[16][4];
        #pragma unroll
        for (int i = 0; i < 16; i++) { acc[i][0] = acc[i][1] = acc[i][2] = acc[i][3] = 0.f; }
        gemm_mat(acc, sb + SA_HI, sb + SA_LO, sb + SB_HI, sb + SB_LO, w, lane);
        #pragma unroll
        for (int nt = 0; nt < 16; nt++) {
            *(float2*)&sD0[r0 * D0_PITCH + nt * 8 + c0] = make_float2(acc[nt][0], acc[nt][1]);
            *(float2*)&sD0[(r0 + 8) * D0_PITCH + nt * 8 + c0] = make_float2(acc[nt][2], acc[nt][3]);
        }
        __syncthreads();
    }

    // ---- matrix 1 (gamma) in regs ----
    float accG[16][4];
    {
        stage32k(sb + SB_HI, prep + 2 * 16384, tid);
        stage32k(sb + SB_LO, prep + 3 * 16384, tid);
        __syncthreads();
        #pragma unroll
        for (int i = 0; i < 16; i++) { accG[i][0] = accG[i][1] = accG[i][2] = accG[i][3] = 0.f; }
        gemm_mat(accG, sb + SA_HI, sb + SA_LO, sb + SB_HI, sb + SB_LO, w, lane);
        __syncthreads();
    }

    // ---- matrix 2 (beta) in regs ----
    float accB[16][4];
    {
        stage32k(sb + SB_HI, prep + 4 * 16384, tid);
        stage32k(sb + SB_LO, prep + 5 * 16384, tid);
        __syncthreads();
        #pragma unroll
        for (int i = 0; i < 16; i++) { accB[i][0] = accB[i][1] = accB[i][2] = accB[i][3] = 0.f; }
        gemm_mat(accB, sb + SA_HI, sb + SA_LO, sb + SB_HI, sb + SB_LO, w, lane);
    }

    // ---- epilogue: msg = relu(gamma*m + beta) ----
    bool okA = (r0 < ntail), okB = (r0 + 8 < ntail);
    float* outA = g_msg + (size_t)(nbase + r0) * 128;
    float* outB = g_msg + (size_t)(nbase + r0 + 8) * 128;
    #pragma unroll
    for (int nt = 0; nt < 16; nt++) {
        float2 mA = *(float2*)&sD0[r0 * D0_PITCH + nt * 8 + c0];
        float2 mB = *(float2*)&sD0[(r0 + 8) * D0_PITCH + nt * 8 + c0];
        if (okA) {
            float2 o;
            o.x = fmaxf(fmaf(accG[nt][0], mA.x, accB[nt][0]), 0.f);
            o.y = fmaxf(fmaf(accG[nt][1], mA.y, accB[nt][1]), 0.f);
            *(float2*)(outA + nt * 8 + c0) = o;
        }
        if (okB) {
            float2 o;
            o.x = fmaxf(fmaf(accG[nt][2], mB.x, accB[nt][2]), 0.f);
            o.y = fmaxf(fmaf(accG[nt][3], mB.y, accB[nt][3]), 0.f);
            *(float2*)(outB + nt * 8 + c0) = o;
        }
    }
}

// ===================== gather (segment sum) + layernorm =====================
// one warp per destination node; 4-way unrolled edge loop for MLP.

__global__ void __launch_bounds__(256)
k_gather_ln(const float* __restrict__ gw, const float* __restrict__ bw, int n) {
    int node = blockIdx.x * 8 + (threadIdx.x >> 5);
    int lane = threadIdx.x & 31;
    if (node >= n) return;
    int beg = g_rowptr[node], end = g_rowptr[node + 1];
    const float4* __restrict__ msg4 = (const float4*)g_msg;
    float4 a0 = make_float4(0.f, 0.f, 0.f, 0.f), a1 = a0, a2 = a0, a3 = a0;
    int i = beg;
    for (; i + 4 <= end; i += 4) {
        int s0 = g_srclist[i + 0], s1 = g_srclist[i + 1];
        int s2 = g_srclist[i + 2], s3 = g_srclist[i + 3];
        float4 v0 = __ldg(&msg4[(size_t)s0 * 32 + lane]);
        float4 v1 = __ldg(&msg4[(size_t)s1 * 32 + lane]);
        float4 v2 = __ldg(&msg4[(size_t)s2 * 32 + lane]);
        float4 v3 = __ldg(&msg4[(size_t)s3 * 32 + lane]);
        a0.x += v0.x; a0.y += v0.y; a0.z += v0.z; a0.w += v0.w;
        a1.x += v1.x; a1.y += v1.y; a1.z += v1.z; a1.w += v1.w;
        a2.x += v2.x; a2.y += v2.y; a2.z += v2.z; a2.w += v2.w;
        a3.x += v3.x; a3.y += v3.y; a3.z += v3.z; a3.w += v3.w;
    }
    for (; i < end; i++) {
        int s = g_srclist[i];
        float4 v = __ldg(&msg4[(size_t)s * 32 + lane]);
        a0.x += v.x; a0.y += v.y; a0.z += v.z; a0.w += v.w;
    }
    float4 a;
    a.x = (a0.x + a1.x) + (a2.x + a3.x);
    a.y = (a0.y + a1.y) + (a2.y + a3.y);
    a.z = (a0.z + a1.z) + (a2.z + a3.z);
    a.w = (a0.w + a1.w) + (a2.w + a3.w);
    float loc = a.x + a.y + a.z + a.w;
    #pragma unroll
    for (int o = 16; o; o >>= 1) loc += __shfl_xor_sync(0xffffffffu, loc, o);
    float mu = loc * (1.0f / 128.0f);
    float d0 = a.x - mu, d1 = a.y - mu, d2 = a.z - mu, d3 = a.w - mu;
    float l2 = d0 * d0 + d1 * d1 + d2 * d2 + d3 * d3;
    #pragma unroll
    for (int o = 16; o; o >>= 1) l2 += __shfl_xor_sync(0xffffffffu, l2, o);
    float rs = rsqrtf(l2 * (1.0f / 128.0f) + LN_EPS);
    float4 gg = __ldg(&((const float4*)gw)[lane]);
    float4 bb = __ldg(&((const float4*)bw)[lane]);
    float4 o4;
    o4.x = d0 * rs * gg.x + bb.x;
    o4.y = d1 * rs * gg.y + bb.y;
    o4.z = d2 * rs * gg.z + bb.z;
    o4.w = d3 * rs * gg.w + bb.w;
    ((float4*)g_h)[(size_t)node * 32 + lane] = o4;
}

// ===================== projection: sigmoid(h @ Wp.T + bp) =====================

#define SMEM_PROJ ((128 * 64 + 64 * 128) * 4)

__global__ void __launch_bounds__(256, 1)
k_proj(const float* __restrict__ Wp, const float* __restrict__ bp,
       float* __restrict__ out, int n) {
    extern __shared__ float smf[];
    float* sWp = smf;
    float* sX = smf + 128 * 64;
    int t = threadIdx.x;
    int nbase = blockIdx.x * 64;
    int nt = n - nbase; if (nt > 64) nt = 64;

    {
        int j = t & 63, seg = t >> 6;
        const float4* w4 = (const float4*)(Wp + (size_t)j * 128);
        #pragma unroll
        for (int kk = 0; kk < 8; kk++) {
            int q = seg * 8 + kk;
            float4 v = w4[q];
            int k = q * 4;
            sWp[(k + 0) * 64 + j] = v.x;
            sWp[(k + 1) * 64 + j] = v.y;
            sWp[(k + 2) * 64 + j] = v.z;
            sWp[(k + 3) * 64 + j] = v.w;
        }
    }
    {
        const float4* x4 = (const float4*)g_h;
        float4* sx4 = (float4*)sX;
        #pragma unroll
        for (int i = 0; i < 8; i++) {
            int idx = t + i * 256;
            int row = idx >> 5, q = idx & 31;
            float4 v = (row < nt) ? x4[(size_t)(nbase + row) * 32 + q]
                                  : make_float4(0.f, 0.f, 0.f, 0.f);
            sx4[row * 32 + q] = v;
        }
    }
    __syncthreads();

    int warp = t >> 5, lane = t & 31;
    int n0 = warp * 8;
    const float* sXb = sX + n0 * 128;
    ull acc[8];
    #pragma unroll
    for (int i = 0; i < 8; i++) acc[i] = 0ull;

    #pragma unroll 4
    for (int k = 0; k < 128; k++) {
        ull wv = *(const ull*)(sWp + k * 64 + 2 * lane);
        #pragma unroll
        for (int i = 0; i < 8; i++)
            acc[i] = ffma2(pack2(sXb[i * 128 + k]), wv, acc[i]);
    }

    float2 bv = ((const float2*)bp)[lane];
    #pragma unroll
    for (int i = 0; i < 8; i++) {
        if (n0 + i < nt) {
            float2 s = unpack2(acc[i]);
            float v0 = 1.0f / (1.0f + __expf(-(s.x + bv.x)));
            float v1 = 1.0f / (1.0f + __expf(-(s.y + bv.y)));
            *(float2*)(out + (size_t)(nbase + n0 + i) * 64 + 2 * lane) = make_float2(v0, v1);
        }
    }
}

// ============================ launch ============================

extern "C" void kernel_launch(void* const* d_in, const int* in_sizes, int n_in,
                              void* d_out, int out_size) {
    const float* feats = (const float*)d_in[0];
    const int*   src   = (const int*)d_in[1];
    const int*   dst   = (const int*)d_in[2];
    const float* W1    = (const float*)d_in[3];
    const float* F1    = (const float*)d_in[4];
    const float* g1    = (const float*)d_in[5];
    const float* b1    = (const float*)d_in[6];
    const float* W2    = (const float*)d_in[7];
    const float* F2    = (const float*)d_in[8];
    const float* g2    = (const float*)d_in[9];
    const float* b2    = (const float*)d_in[10];
    const float* Wp    = (const float*)d_in[11];
    const float* bp    = (const float*)d_in[12];
    float* out = (float*)d_out;

    int n = in_sizes[0] / 128;   // 50000
    int e = in_sizes[1];         // 600000

    cudaFuncSetAttribute(k_film_mma, cudaFuncAttributeMaxDynamicSharedMemorySize, SMEM_MMA);
    cudaFuncSetAttribute(k_proj, cudaFuncAttributeMaxDynamicSharedMemorySize, SMEM_PROJ);

    int mtiles = (n + 127) / 128;
    int ptiles = (n + 63) / 64;

    // weight prep (bf16 hi/lo) + CSR build
    k_prep<<<6, 256>>>(W1, F1, W2, F2);
    k_zero<<<(n + 255) / 256, 256>>>(n);
    k_count<<<(e + 255) / 256, 256>>>(dst, e);
    k_scan<<<1, 1024>>>(n, e);
    k_fill<<<(e + 255) / 256, 256>>>(src, dst, e);

    // layer 1
    k_film_mma<<<mtiles, 256, SMEM_MMA>>>(feats, 0, 0, n);
    k_gather_ln<<<(n + 7) / 8, 256>>>(g1, b1, n);
    // layer 2
    k_film_mma<<<mtiles, 256, SMEM_MMA>>>(nullptr, 1, 1, n);
    k_gather_ln<<<(n + 7) / 8, 256>>>(g2, b2, n);
    // projection
    k_proj<<<ptiles, 256, SMEM_PROJ>>>(Wp, bp, out, n);
}

// round 13
// speedup vs baseline: 2.0405x; 1.1659x over previous
#include <cuda_runtime.h>
#include <cuda_bf16.h>

#define NN 50000
#define EE 600000
#define LN_EPS 1e-5f

typedef unsigned long long ull;
typedef unsigned int u32;

// ---- scratch (device globals; no allocations allowed) ----
__device__ float g_msg[(size_t)NN * 128];
__device__ float g_h[(size_t)NN * 128];
__device__ int   g_rowptr[NN + 1];
__device__ int   g_counts[NN];
__device__ int   g_cursor[NN];
__device__ int   g_srclist[EE];
__device__ int   g_partials[256];
// row-major bf16 hi/lo weights: [layer][matrix 0..2][hi/lo][128*128]
__device__ __align__(16) __nv_bfloat16 g_wprep[2][3][2][16384];

// ============================ helpers ============================

__device__ __forceinline__ u32 smem_u32(const void* p) {
    u32 a;
    asm("{ .reg .u64 t; cvta.to.shared.u64 t, %1; cvt.u32.u64 %0, t; }" : "=r"(a) : "l"(p));
    return a;
}
__device__ __forceinline__ void ldsm_x4(u32& r0, u32& r1, u32& r2, u32& r3, u32 addr) {
    asm volatile("ldmatrix.sync.aligned.m8n8.x4.shared.b16 {%0,%1,%2,%3}, [%4];"
                 : "=r"(r0), "=r"(r1), "=r"(r2), "=r"(r3) : "r"(addr));
}
__device__ __forceinline__ void mma16816(float* d, const u32* a, u32 b0, u32 b1) {
    asm volatile(
        "mma.sync.aligned.m16n8k16.row.col.f32.bf16.bf16.f32 "
        "{%0,%1,%2,%3}, {%4,%5,%6,%7}, {%8,%9}, {%0,%1,%2,%3};"
        : "+f"(d[0]), "+f"(d[1]), "+f"(d[2]), "+f"(d[3])
        : "r"(a[0]), "r"(a[1]), "r"(a[2]), "r"(a[3]), "r"(b0), "r"(b1));
}

// ---- packed f32x2 helpers (proj kernel) ----
__device__ __forceinline__ ull ffma2(ull a, ull b, ull c) {
    ull d;
    asm("fma.rn.f32x2 %0, %1, %2, %3;" : "=l"(d) : "l"(a), "l"(b), "l"(c));
    return d;
}
__device__ __forceinline__ ull pack2(float x) {
    ull d;
    asm("mov.b64 %0, {%1, %1};" : "=l"(d) : "f"(x));
    return d;
}
__device__ __forceinline__ float2 unpack2(ull v) {
    float2 r;
    asm("mov.b64 {%0, %1}, %2;" : "=f"(r.x), "=f"(r.y) : "l"(v));
    return r;
}

// ============================ CSR build ============================

__global__ void k_zero(int n) {
    int i = blockIdx.x * blockDim.x + threadIdx.x;
    if (i < n) { g_counts[i] = 0; g_cursor[i] = 0; }
}
__global__ void k_count(const int* __restrict__ dst, int e) {
    int i = blockIdx.x * blockDim.x + threadIdx.x;
    if (i < e) atomicAdd(&g_counts[dst[i]], 1);
}

// ---- 3-phase full-chip exclusive scan of g_counts -> g_rowptr ----

__global__ void k_scan_a(int n) {
    int tid = threadIdx.x, lane = tid & 31, w = tid >> 5;
    int i = blockIdx.x * 256 + tid;
    int v = (i < n) ? g_counts[i] : 0;
    #pragma unroll
    for (int o = 16; o; o >>= 1) v += __shfl_xor_sync(0xffffffffu, v, o);
    __shared__ int ws[8];
    if (lane == 0) ws[w] = v;
    __syncthreads();
    if (tid == 0) {
        int s = 0;
        #pragma unroll
        for (int q = 0; q < 8; q++) s += ws[q];
        g_partials[blockIdx.x] = s;
    }
}

__global__ void k_scan_b(int nb) {
    int tid = threadIdx.x, lane = tid & 31, w = tid >> 5;
    int v = (tid < nb) ? g_partials[tid] : 0;
    int x = v;
    #pragma unroll
    for (int o = 1; o < 32; o <<= 1) {
        int t = __shfl_up_sync(0xffffffffu, x, o);
        if (lane >= o) x += t;
    }
    __shared__ int ws[8];
    if (lane == 31) ws[w] = x;
    __syncthreads();
    if (w == 0) {
        int y = (lane < 8) ? ws[lane] : 0;
        #pragma unroll
        for (int o = 1; o < 8; o <<= 1) {
            int t = __shfl_up_sync(0xffffffffu, y, o);
            if (lane >= o) y += t;
        }
        if (lane < 8) ws[lane] = y;
    }
    __syncthreads();
    int incl = x + (w ? ws[w - 1] : 0);
    if (tid < nb) g_partials[tid] = incl - v;   // exclusive
}

__global__ void k_scan_c(int n, int e) {
    int tid = threadIdx.x, lane = tid & 31, w = tid >> 5;
    int i = blockIdx.x * 256 + tid;
    int v = (i < n) ? g_counts[i] : 0;
    int x = v;
    #pragma unroll
    for (int o = 1; o < 32; o <<= 1) {
        int t = __shfl_up_sync(0xffffffffu, x, o);
        if (lane >= o) x += t;
    }
    __shared__ int ws[8];
    if (lane == 31) ws[w] = x;
    __syncthreads();
    if (w == 0) {
        int y = (lane < 8) ? ws[lane] : 0;
        #pragma unroll
        for (int o = 1; o < 8; o <<= 1) {
            int t = __shfl_up_sync(0xffffffffu, y, o);
            if (lane >= o) y += t;
        }
        if (lane < 8) ws[lane] = y;
    }
    __syncthreads();
    int incl = x + (w ? ws[w - 1] : 0);
    int excl = incl - v + g_partials[blockIdx.x];
    if (i < n) g_rowptr[i] = excl;
    if (i == 0 && blockIdx.x == 0) g_rowptr[n] = e;
}

__global__ void k_fill(const int* __restrict__ src, const int* __restrict__ dst, int e) {
    int i = blockIdx.x * blockDim.x + threadIdx.x;
    if (i < e) {
        int d = dst[i];
        int slot = g_rowptr[d] + atomicAdd(&g_cursor[d], 1);
        g_srclist[slot] = src[i];
    }
}

// ==================== weight prep: fp32 -> row-major bf16 hi/lo ====================

__global__ void k_prep(const float* __restrict__ W1, const float* __restrict__ F1,
                       const float* __restrict__ W2, const float* __restrict__ F2) {
    int b = blockIdx.x;           // 0..5
    int layer = b / 3, m = b % 3;
    const float* src;
    if (layer == 0) src = (m == 0) ? W1 : (F1 + (m - 1) * 16384);
    else            src = (m == 0) ? W2 : (F2 + (m - 1) * 16384);
    __nv_bfloat16* dhi = &g_wprep[layer][m][0][0];
    __nv_bfloat16* dlo = &g_wprep[layer][m][1][0];
    for (int i = threadIdx.x; i < 16384; i += blockDim.x) {
        float v = src[i];
        __nv_bfloat16 h = __float2bfloat16(v);
        __nv_bfloat16 l = __float2bfloat16(v - __bfloat162float(h));
        dhi[i] = h;
        dlo[i] = l;
    }
}

// ============================ FiLM GEMM (mma.sync bf16) ============================
// CTA: 128 nodes x 384 outputs, 8 warps, each warp 16 rows x 128 cols.
// D = Ah*Bh + Al*Bh + Ah*Bl per matrix. First matrix (m) stashed to smem fp32;
// gamma/beta kept in regs. Epilogue: msg = relu(gamma*m + beta).

// smem layout (bytes)
#define SA_HI 0
#define SA_LO 32768
#define SB_HI 65536
#define SB_LO 98304
#define SD0   131072
#define D0_PITCH 132
#define SMEM_MMA (131072 + 128 * D0_PITCH * 4)   // 198656

// chunk swizzle: 16B chunks, pitch 256B (16 chunks/row)
__device__ __forceinline__ u32 sw_addr(u32 base, int row, int chunk) {
    return base + (u32)row * 256u + (u32)((chunk ^ (row & 7)) << 4);
}

// stage one 128x128 bf16 matrix (32KB) from global row-major into swizzled smem
__device__ __forceinline__ void stage32k(u32 sdst, const __nv_bfloat16* src, int tid) {
    const uint4* s4 = (const uint4*)src;
    #pragma unroll
    for (int it = 0; it < 8; it++) {
        int idx = tid + it * 256;          // 0..2047 chunks
        int row = idx >> 4, c = idx & 15;
        uint4 v = __ldg(&s4[idx]);
        asm volatile("st.shared.v4.b32 [%0], {%1,%2,%3,%4};"
                     :: "r"(sw_addr(sdst, row, c)), "r"(v.x), "r"(v.y), "r"(v.z), "r"(v.w));
    }
}

// compute one 128x128 matrix product into acc[16][4]
__device__ __forceinline__ void gemm_mat(float acc[16][4], u32 sAhi, u32 sAlo,
                                         u32 sBhi, u32 sBlo, int w, int lane) {
    int tile = lane >> 3;                 // 0..3
    int rA = 16 * w + (tile & 1) * 8 + (lane & 7);
    int rAs = rA & 7;
    int hiA = tile >> 1;
    u32 aHiRow = sAhi + (u32)rA * 256u;
    u32 aLoRow = sAlo + (u32)rA * 256u;
    int rB = (tile & 1) * 8 + (lane & 7);
    int rBs = rB & 7;
    int hiB = tile >> 1;

    #pragma unroll
    for (int kt = 0; kt < 8; kt++) {
        u32 ah[4], al[4];
        u32 aoff = (u32)(((kt * 2 + hiA) ^ rAs) << 4);
        ldsm_x4(ah[0], ah[1], ah[2], ah[3], aHiRow + aoff);
        ldsm_x4(al[0], al[1], al[2], al[3], aLoRow + aoff);
        #pragma unroll
        for (int nt2 = 0; nt2 < 8; nt2++) {
            int rowB = nt2 * 16 + rB;
            u32 boff = (u32)rowB * 256u + (u32)(((kt * 2 + hiB) ^ rBs) << 4);
            u32 bh[4], bl[4];
            ldsm_x4(bh[0], bh[1], bh[2], bh[3], sBhi + boff);
            ldsm_x4(bl[0], bl[1], bl[2], bl[3], sBlo + boff);
            mma16816(acc[2 * nt2 + 0], ah, bh[0], bh[2]);
            mma16816(acc[2 * nt2 + 0], al, bh[0], bh[2]);
            mma16816(acc[2 * nt2 + 0], ah, bl[0], bl[2]);
            mma16816(acc[2 * nt2 + 1], ah, bh[1], bh[3]);
            mma16816(acc[2 * nt2 + 1], al, bh[1], bh[3]);
            mma16816(acc[2 * nt2 + 1], ah, bl[1], bl[3]);
        }
    }
}

__global__ void __launch_bounds__(256, 1)
k_film_mma(const float* __restrict__ Xext, int use_internal, int layer, int n) {
    extern __shared__ char sm[];
    u32 sb = smem_u32(sm);
    float* sD0 = (float*)(sm + SD0);
    int tid = threadIdx.x, w = tid >> 5, lane = tid & 31;
    const float* X = use_internal ? g_h : Xext;
    int nbase = blockIdx.x * 128;
    int ntail = n - nbase; if (ntail > 128) ntail = 128;

    // zero A smem only for the tail tile
    if (ntail < 128) {
        #pragma unroll
        for (int i = 0; i < 16; i++) {
            asm volatile("st.shared.v4.b32 [%0], {%1,%1,%1,%1};"
                         :: "r"(sb + SA_HI + (u32)(tid * 16 + i * 4096)), "r"(0u));
        }
    }
    __syncthreads();

    // ---- convert X tile to bf16 hi/lo, swizzled ----
    #pragma unroll
    for (int it = 0; it < 8; it++) {
        int idx = tid + it * 256;          // 2048 chunks
        int row = idx >> 4, c = idx & 15;
        if (row < ntail) {
            const float* xp = X + (size_t)(nbase + row) * 128 + c * 8;
            float4 v0 = *(const float4*)xp;
            float4 v1 = *(const float4*)(xp + 4);
            float f[8] = {v0.x, v0.y, v0.z, v0.w, v1.x, v1.y, v1.z, v1.w};
            u32 hp[4], lp[4];
            #pragma unroll
            for (int q = 0; q < 4; q++) {
                __nv_bfloat16 h0 = __float2bfloat16(f[2 * q]);
                __nv_bfloat16 h1 = __float2bfloat16(f[2 * q + 1]);
                __nv_bfloat16 l0 = __float2bfloat16(f[2 * q] - __bfloat162float(h0));
                __nv_bfloat16 l1 = __float2bfloat16(f[2 * q + 1] - __bfloat162float(h1));
                __nv_bfloat162 hh; hh.x = h0; hh.y = h1;
                __nv_bfloat162 ll; ll.x = l0; ll.y = l1;
                hp[q] = *(u32*)&hh;
                lp[q] = *(u32*)&ll;
            }
            asm volatile("st.shared.v4.b32 [%0], {%1,%2,%3,%4};"
                         :: "r"(sw_addr(sb + SA_HI, row, c)), "r"(hp[0]), "r"(hp[1]), "r"(hp[2]), "r"(hp[3]));
            asm volatile("st.shared.v4.b32 [%0], {%1,%2,%3,%4};"
                         :: "r"(sw_addr(sb + SA_LO, row, c)), "r"(lp[0]), "r"(lp[1]), "r"(lp[2]), "r"(lp[3]));
        }
    }

    const __nv_bfloat16* prep = &g_wprep[layer][0][0][0];
    int r0 = 16 * w + (lane >> 2);
    int c0 = 2 * (lane & 3);

    // ---- matrix 0 (W -> m), stash to smem fp32 ----
    {
        stage32k(sb + SB_HI, prep, tid);
        stage32k(sb + SB_LO, prep + 16384, tid);
        __syncthreads();
        float acc[16][4];
        #pragma unroll
        for (int i = 0; i < 16; i++) { acc[i][0] = acc[i][1] = acc[i][2] = acc[i][3] = 0.f; }
        gemm_mat(acc, sb + SA_HI, sb + SA_LO, sb + SB_HI, sb + SB_LO, w, lane);
        #pragma unroll
        for (int nt = 0; nt < 16; nt++) {
            *(float2*)&sD0[r0 * D0_PITCH + nt * 8 + c0] = make_float2(acc[nt][0], acc[nt][1]);
            *(float2*)&sD0[(r0 + 8) * D0_PITCH + nt * 8 + c0] = make_float2(acc[nt][2], acc[nt][3]);
        }
        __syncthreads();
    }

    // ---- matrix 1 (gamma) in regs ----
    float accG[16][4];
    {
        stage32k(sb + SB_HI, prep + 2 * 16384, tid);
        stage32k(sb + SB_LO, prep + 3 * 16384, tid);
        __syncthreads();
        #pragma unroll
        for (int i = 0; i < 16; i++) { accG[i][0] = accG[i][1] = accG[i][2] = accG[i][3] = 0.f; }
        gemm_mat(accG, sb + SA_HI, sb + SA_LO, sb + SB_HI, sb + SB_LO, w, lane);
        __syncthreads();
    }

    // ---- matrix 2 (beta) in regs ----
    float accB[16][4];
    {
        stage32k(sb + SB_HI, prep + 4 * 16384, tid);
        stage32k(sb + SB_LO, prep + 5 * 16384, tid);
        __syncthreads();
        #pragma unroll
        for (int i = 0; i < 16; i++) { accB[i][0] = accB[i][1] = accB[i][2] = accB[i][3] = 0.f; }
        gemm_mat(accB, sb + SA_HI, sb + SA_LO, sb + SB_HI, sb + SB_LO, w, lane);
    }

    // ---- epilogue: msg = relu(gamma*m + beta) ----
    bool okA = (r0 < ntail), okB = (r0 + 8 < ntail);
    float* outA = g_msg + (size_t)(nbase + r0) * 128;
    float* outB = g_msg + (size_t)(nbase + r0 + 8) * 128;
    #pragma unroll
    for (int nt = 0; nt < 16; nt++) {
        float2 mA = *(float2*)&sD0[r0 * D0_PITCH + nt * 8 + c0];
        float2 mB = *(float2*)&sD0[(r0 + 8) * D0_PITCH + nt * 8 + c0];
        if (okA) {
            float2 o;
            o.x = fmaxf(fmaf(accG[nt][0], mA.x, accB[nt][0]), 0.f);
            o.y = fmaxf(fmaf(accG[nt][1], mA.y, accB[nt][1]), 0.f);
            *(float2*)(outA + nt * 8 + c0) = o;
        }
        if (okB) {
            float2 o;
            o.x = fmaxf(fmaf(accG[nt][2], mB.x, accB[nt][2]), 0.f);
            o.y = fmaxf(fmaf(accG[nt][3], mB.y, accB[nt][3]), 0.f);
            *(float2*)(outB + nt * 8 + c0) = o;
        }
    }
}

// ===================== gather (segment sum) + layernorm =====================
// one warp per destination node; 4-way unrolled edge loop for MLP.

__global__ void __launch_bounds__(256)
k_gather_ln(const float* __restrict__ gw, const float* __restrict__ bw, int n) {
    int node = blockIdx.x * 8 + (threadIdx.x >> 5);
    int lane = threadIdx.x & 31;
    if (node >= n) return;
    int beg = g_rowptr[node], end = g_rowptr[node + 1];
    const float4* __restrict__ msg4 = (const float4*)g_msg;
    float4 a0 = make_float4(0.f, 0.f, 0.f, 0.f), a1 = a0, a2 = a0, a3 = a0;
    int i = beg;
    for (; i + 4 <= end; i += 4) {
        int s0 = g_srclist[i + 0], s1 = g_srclist[i + 1];
        int s2 = g_srclist[i + 2], s3 = g_srclist[i + 3];
        float4 v0 = __ldg(&msg4[(size_t)s0 * 32 + lane]);
        float4 v1 = __ldg(&msg4[(size_t)s1 * 32 + lane]);
        float4 v2 = __ldg(&msg4[(size_t)s2 * 32 + lane]);
        float4 v3 = __ldg(&msg4[(size_t)s3 * 32 + lane]);
        a0.x += v0.x; a0.y += v0.y; a0.z += v0.z; a0.w += v0.w;
        a1.x += v1.x; a1.y += v1.y; a1.z += v1.z; a1.w += v1.w;
        a2.x += v2.x; a2.y += v2.y; a2.z += v2.z; a2.w += v2.w;
        a3.x += v3.x; a3.y += v3.y; a3.z += v3.z; a3.w += v3.w;
    }
    for (; i < end; i++) {
        int s = g_srclist[i];
        float4 v = __ldg(&msg4[(size_t)s * 32 + lane]);
        a0.x += v.x; a0.y += v.y; a0.z += v.z; a0.w += v.w;
    }
    float4 a;
    a.x = (a0.x + a1.x) + (a2.x + a3.x);
    a.y = (a0.y + a1.y) + (a2.y + a3.y);
    a.z = (a0.z + a1.z) + (a2.z + a3.z);
    a.w = (a0.w + a1.w) + (a2.w + a3.w);
    float loc = a.x + a.y + a.z + a.w;
    #pragma unroll
    for (int o = 16; o; o >>= 1) loc += __shfl_xor_sync(0xffffffffu, loc, o);
    float mu = loc * (1.0f / 128.0f);
    float d0 = a.x - mu, d1 = a.y - mu, d2 = a.z - mu, d3 = a.w - mu;
    float l2 = d0 * d0 + d1 * d1 + d2 * d2 + d3 * d3;
    #pragma unroll
    for (int o = 16; o; o >>= 1) l2 += __shfl_xor_sync(0xffffffffu, l2, o);
    float rs = rsqrtf(l2 * (1.0f / 128.0f) + LN_EPS);
    float4 gg = __ldg(&((const float4*)gw)[lane]);
    float4 bb = __ldg(&((const float4*)bw)[lane]);
    float4 o4;
    o4.x = d0 * rs * gg.x + bb.x;
    o4.y = d1 * rs * gg.y + bb.y;
    o4.z = d2 * rs * gg.z + bb.z;
    o4.w = d3 * rs * gg.w + bb.w;
    ((float4*)g_h)[(size_t)node * 32 + lane] = o4;
}

// ===================== projection: sigmoid(h @ Wp.T + bp) =====================

#define SMEM_PROJ ((128 * 64 + 64 * 128) * 4)

__global__ void __launch_bounds__(256, 1)
k_proj(const float* __restrict__ Wp, const float* __restrict__ bp,
       float* __restrict__ out, int n) {
    extern __shared__ float smf[];
    float* sWp = smf;
    float* sX = smf + 128 * 64;
    int t = threadIdx.x;
    int nbase = blockIdx.x * 64;
    int nt = n - nbase; if (nt > 64) nt = 64;

    {
        int j = t & 63, seg = t >> 6;
        const float4* w4 = (const float4*)(Wp + (size_t)j * 128);
        #pragma unroll
        for (int kk = 0; kk < 8; kk++) {
            int q = seg * 8 + kk;
            float4 v = w4[q];
            int k = q * 4;
            sWp[(k + 0) * 64 + j] = v.x;
            sWp[(k + 1) * 64 + j] = v.y;
            sWp[(k + 2) * 64 + j] = v.z;
            sWp[(k + 3) * 64 + j] = v.w;
        }
    }
    {
        const float4* x4 = (const float4*)g_h;
        float4* sx4 = (float4*)sX;
        #pragma unroll
        for (int i = 0; i < 8; i++) {
            int idx = t + i * 256;
            int row = idx >> 5, q = idx & 31;
            float4 v = (row < nt) ? x4[(size_t)(nbase + row) * 32 + q]
                                  : make_float4(0.f, 0.f, 0.f, 0.f);
            sx4[row * 32 + q] = v;
        }
    }
    __syncthreads();

    int warp = t >> 5, lane = t & 31;
    int n0 = warp * 8;
    const float* sXb = sX + n0 * 128;
    ull acc[8];
    #pragma unroll
    for (int i = 0; i < 8; i++) acc[i] = 0ull;

    #pragma unroll 4
    for (int k = 0; k < 128; k++) {
        ull wv = *(const ull*)(sWp + k * 64 + 2 * lane);
        #pragma unroll
        for (int i = 0; i < 8; i++)
            acc[i] = ffma2(pack2(sXb[i * 128 + k]), wv, acc[i]);
    }

    float2 bv = ((const float2*)bp)[lane];
    #pragma unroll
    for (int i = 0; i < 8; i++) {
        if (n0 + i < nt) {
            float2 s = unpack2(acc[i]);
            float v0 = 1.0f / (1.0f + __expf(-(s.x + bv.x)));
            float v1 = 1.0f / (1.0f + __expf(-(s.y + bv.y)));
            *(float2*)(out + (size_t)(nbase + n0 + i) * 64 + 2 * lane) = make_float2(v0, v1);
        }
    }
}

// ============================ launch ============================

extern "C" void kernel_launch(void* const* d_in, const int* in_sizes, int n_in,
                              void* d_out, int out_size) {
    const float* feats = (const float*)d_in[0];
    const int*   src   = (const int*)d_in[1];
    const int*   dst   = (const int*)d_in[2];
    const float* W1    = (const float*)d_in[3];
    const float* F1    = (const float*)d_in[4];
    const float* g1    = (const float*)d_in[5];
    const float* b1    = (const float*)d_in[6];
    const float* W2    = (const float*)d_in[7];
    const float* F2    = (const float*)d_in[8];
    const float* g2    = (const float*)d_in[9];
    const float* b2    = (const float*)d_in[10];
    const float* Wp    = (const float*)d_in[11];
    const float* bp    = (const float*)d_in[12];
    float* out = (float*)d_out;

    int n = in_sizes[0] / 128;   // 50000
    int e = in_sizes[1];         // 600000

    cudaFuncSetAttribute(k_film_mma, cudaFuncAttributeMaxDynamicSharedMemorySize, SMEM_MMA);
    cudaFuncSetAttribute(k_proj, cudaFuncAttributeMaxDynamicSharedMemorySize, SMEM_PROJ);

    int mtiles = (n + 127) / 128;
    int ptiles = (n + 63) / 64;
    int nb = (n + 255) / 256;    // scan blocks (196)

    // weight prep (bf16 hi/lo) + CSR build
    k_prep<<<6, 256>>>(W1, F1, W2, F2);
    k_zero<<<(n + 255) / 256, 256>>>(n);
    k_count<<<(e + 255) / 256, 256>>>(dst, e);
    k_scan_a<<<nb, 256>>>(n);
    k_scan_b<<<1, 256>>>(nb);
    k_scan_c<<<nb, 256>>>(n, e);
    k_fill<<<(e + 255) / 256, 256>>>(src, dst, e);

    // layer 1
    k_film_mma<<<mtiles, 256, SMEM_MMA>>>(feats, 0, 0, n);
    k_gather_ln<<<(n + 7) / 8, 256>>>(g1, b1, n);
    // layer 2
    k_film_mma<<<mtiles, 256, SMEM_MMA>>>(nullptr, 1, 1, n);
    k_gather_ln<<<(n + 7) / 8, 256>>>(g2, b2, n);
    // projection
    k_proj<<<ptiles, 256, SMEM_PROJ>>>(Wp, bp, out, n);
}

// round 14
// speedup vs baseline: 2.1404x; 1.0489x over previous
#include <cuda_runtime.h>
#include <cuda_bf16.h>

#define NN 50000
#define EE 600000
#define LN_EPS 1e-5f

typedef unsigned long long ull;
typedef unsigned int u32;

// ---- scratch (device globals; no allocations allowed) ----
__device__ float g_msg[(size_t)NN * 128];
__device__ float g_h[(size_t)NN * 128];
__device__ int   g_rowptr[NN + 1];
__device__ int   g_counts[NN];
__device__ int   g_cursor[NN];
__device__ int   g_srclist[EE];
__device__ int   g_partials[256];
// row-major bf16 hi/lo weights: [layer][matrix 0..2][hi/lo][128*128]
__device__ __align__(16) __nv_bfloat16 g_wprep[2][3][2][16384];

// ============================ helpers ============================

__device__ __forceinline__ u32 smem_u32(const void* p) {
    u32 a;
    asm("{ .reg .u64 t; cvta.to.shared.u64 t, %1; cvt.u32.u64 %0, t; }" : "=r"(a) : "l"(p));
    return a;
}
__device__ __forceinline__ void ldsm_x4(u32& r0, u32& r1, u32& r2, u32& r3, u32 addr) {
    asm volatile("ldmatrix.sync.aligned.m8n8.x4.shared.b16 {%0,%1,%2,%3}, [%4];"
                 : "=r"(r0), "=r"(r1), "=r"(r2), "=r"(r3) : "r"(addr));
}
__device__ __forceinline__ void mma16816(float* d, const u32* a, u32 b0, u32 b1) {
    asm volatile(
        "mma.sync.aligned.m16n8k16.row.col.f32.bf16.bf16.f32 "
        "{%0,%1,%2,%3}, {%4,%5,%6,%7}, {%8,%9}, {%0,%1,%2,%3};"
        : "+f"(d[0]), "+f"(d[1]), "+f"(d[2]), "+f"(d[3])
        : "r"(a[0]), "r"(a[1]), "r"(a[2]), "r"(a[3]), "r"(b0), "r"(b1));
}

// ---- packed f32x2 helpers (proj kernel) ----
__device__ __forceinline__ ull ffma2(ull a, ull b, ull c) {
    ull d;
    asm("fma.rn.f32x2 %0, %1, %2, %3;" : "=l"(d) : "l"(a), "l"(b), "l"(c));
    return d;
}
__device__ __forceinline__ ull pack2(float x) {
    ull d;
    asm("mov.b64 %0, {%1, %1};" : "=l"(d) : "f"(x));
    return d;
}
__device__ __forceinline__ float2 unpack2(ull v) {
    float2 r;
    asm("mov.b64 {%0, %1}, %2;" : "=f"(r.x), "=f"(r.y) : "l"(v));
    return r;
}

// ============================ CSR build ============================

__global__ void k_zero(int n) {
    int i = blockIdx.x * blockDim.x + threadIdx.x;
    if (i < n) { g_counts[i] = 0; g_cursor[i] = 0; }
}
__global__ void k_count(const int* __restrict__ dst, int e) {
    int i = blockIdx.x * blockDim.x + threadIdx.x;
    if (i < e) atomicAdd(&g_counts[dst[i]], 1);
}

// ---- 3-phase full-chip exclusive scan of g_counts -> g_rowptr ----

__global__ void k_scan_a(int n) {
    int tid = threadIdx.x, lane = tid & 31, w = tid >> 5;
    int i = blockIdx.x * 256 + tid;
    int v = (i < n) ? g_counts[i] : 0;
    #pragma unroll
    for (int o = 16; o; o >>= 1) v += __shfl_xor_sync(0xffffffffu, v, o);
    __shared__ int ws[8];
    if (lane == 0) ws[w] = v;
    __syncthreads();
    if (tid == 0) {
        int s = 0;
        #pragma unroll
        for (int q = 0; q < 8; q++) s += ws[q];
        g_partials[blockIdx.x] = s;
    }
}

__global__ void k_scan_b(int nb) {
    int tid = threadIdx.x, lane = tid & 31, w = tid >> 5;
    int v = (tid < nb) ? g_partials[tid] : 0;
    int x = v;
    #pragma unroll
    for (int o = 1; o < 32; o <<= 1) {
        int t = __shfl_up_sync(0xffffffffu, x, o);
        if (lane >= o) x += t;
    }
    __shared__ int ws[8];
    if (lane == 31) ws[w] = x;
    __syncthreads();
    if (w == 0) {
        int y = (lane < 8) ? ws[lane] : 0;
        #pragma unroll
        for (int o = 1; o < 8; o <<= 1) {
            int t = __shfl_up_sync(0xffffffffu, y, o);
            if (lane >= o) y += t;
        }
        if (lane < 8) ws[lane] = y;
    }
    __syncthreads();
    int incl = x + (w ? ws[w - 1] : 0);
    if (tid < nb) g_partials[tid] = incl - v;   // exclusive
}

__global__ void k_scan_c(int n, int e) {
    int tid = threadIdx.x, lane = tid & 31, w = tid >> 5;
    int i = blockIdx.x * 256 + tid;
    int v = (i < n) ? g_counts[i] : 0;
    int x = v;
    #pragma unroll
    for (int o = 1; o < 32; o <<= 1) {
        int t = __shfl_up_sync(0xffffffffu, x, o);
        if (lane >= o) x += t;
    }
    __shared__ int ws[8];
    if (lane == 31) ws[w] = x;
    __syncthreads();
    if (w == 0) {
        int y = (lane < 8) ? ws[lane] : 0;
        #pragma unroll
        for (int o = 1; o < 8; o <<= 1) {
            int t = __shfl_up_sync(0xffffffffu, y, o);
            if (lane >= o) y += t;
        }
        if (lane < 8) ws[lane] = y;
    }
    __syncthreads();
    int incl = x + (w ? ws[w - 1] : 0);
    int excl = incl - v + g_partials[blockIdx.x];
    if (i < n) g_rowptr[i] = excl;
    if (i == 0 && blockIdx.x == 0) g_rowptr[n] = e;
}

__global__ void k_fill(const int* __restrict__ src, const int* __restrict__ dst, int e) {
    int i = blockIdx.x * blockDim.x + threadIdx.x;
    if (i < e) {
        int d = dst[i];
        int slot = g_rowptr[d] + atomicAdd(&g_cursor[d], 1);
        g_srclist[slot] = src[i];
    }
}

// ==================== weight prep: fp32 -> row-major bf16 hi/lo ====================

__global__ void k_prep(const float* __restrict__ W1, const float* __restrict__ F1,
                       const float* __restrict__ W2, const float* __restrict__ F2) {
    int b = blockIdx.x;           // 0..5
    int layer = b / 3, m = b % 3;
    const float* src;
    if (layer == 0) src = (m == 0) ? W1 : (F1 + (m - 1) * 16384);
    else            src = (m == 0) ? W2 : (F2 + (m - 1) * 16384);
    __nv_bfloat16* dhi = &g_wprep[layer][m][0][0];
    __nv_bfloat16* dlo = &g_wprep[layer][m][1][0];
    for (int i = threadIdx.x; i < 16384; i += blockDim.x) {
        float v = src[i];
        __nv_bfloat16 h = __float2bfloat16(v);
        __nv_bfloat16 l = __float2bfloat16(v - __bfloat162float(h));
        dhi[i] = h;
        dlo[i] = l;
    }
}

// ============================ FiLM GEMM (mma.sync bf16) ============================
// CTA: 128 nodes x 384 outputs, 8 warps, each warp 16 rows x 128 cols.
// D = Ah*Bh + Al*Bh + Ah*Bl per matrix. First matrix (m) stashed to smem fp32;
// gamma/beta kept in regs. Epilogue: msg = relu(gamma*m + beta).

// smem layout (bytes)
#define SA_HI 0
#define SA_LO 32768
#define SB_HI 65536
#define SB_LO 98304
#define SD0   131072
#define D0_PITCH 132
#define SMEM_MMA (131072 + 128 * D0_PITCH * 4)   // 198656

// chunk swizzle: 16B chunks, pitch 256B (16 chunks/row)
__device__ __forceinline__ u32 sw_addr(u32 base, int row, int chunk) {
    return base + (u32)row * 256u + (u32)((chunk ^ (row & 7)) << 4);
}

// stage one 128x128 bf16 matrix (32KB) from global row-major into swizzled smem
__device__ __forceinline__ void stage32k(u32 sdst, const __nv_bfloat16* src, int tid) {
    const uint4* s4 = (const uint4*)src;
    #pragma unroll
    for (int it = 0; it < 8; it++) {
        int idx = tid + it * 256;          // 0..2047 chunks
        int row = idx >> 4, c = idx & 15;
        uint4 v = __ldg(&s4[idx]);
        asm volatile("st.shared.v4.b32 [%0], {%1,%2,%3,%4};"
                     :: "r"(sw_addr(sdst, row, c)), "r"(v.x), "r"(v.y), "r"(v.z), "r"(v.w));
    }
}

// compute one 128x128 matrix product into acc[16][4]
__device__ __forceinline__ void gemm_mat(float acc[16][4], u32 sAhi, u32 sAlo,
                                         u32 sBhi, u32 sBlo, int w, int lane) {
    int tile = lane >> 3;                 // 0..3
    int rA = 16 * w + (tile & 1) * 8 + (lane & 7);
    int rAs = rA & 7;
    int hiA = tile >> 1;
    u32 aHiRow = sAhi + (u32)rA * 256u;
    u32 aLoRow = sAlo + (u32)rA * 256u;
    int rB = (tile & 1) * 8 + (lane & 7);
    int rBs = rB & 7;
    int hiB = tile >> 1;

    #pragma unroll
    for (int kt = 0; kt < 8; kt++) {
        u32 ah[4], al[4];
        u32 aoff = (u32)(((kt * 2 + hiA) ^ rAs) << 4);
        ldsm_x4(ah[0], ah[1], ah[2], ah[3], aHiRow + aoff);
        ldsm_x4(al[0], al[1], al[2], al[3], aLoRow + aoff);
        #pragma unroll
        for (int nt2 = 0; nt2 < 8; nt2++) {
            int rowB = nt2 * 16 + rB;
            u32 boff = (u32)rowB * 256u + (u32)(((kt * 2 + hiB) ^ rBs) << 4);
            u32 bh[4], bl[4];
            ldsm_x4(bh[0], bh[1], bh[2], bh[3], sBhi + boff);
            ldsm_x4(bl[0], bl[1], bl[2], bl[3], sBlo + boff);
            mma16816(acc[2 * nt2 + 0], ah, bh[0], bh[2]);
            mma16816(acc[2 * nt2 + 0], al, bh[0], bh[2]);
            mma16816(acc[2 * nt2 + 0], ah, bl[0], bl[2]);
            mma16816(acc[2 * nt2 + 1], ah, bh[1], bh[3]);
            mma16816(acc[2 * nt2 + 1], al, bh[1], bh[3]);
            mma16816(acc[2 * nt2 + 1], ah, bl[1], bl[3]);
        }
    }
}

__global__ void __launch_bounds__(256, 1)
k_film_mma(const float* __restrict__ Xext, int use_internal, int layer, int n) {
    extern __shared__ char sm[];
    u32 sb = smem_u32(sm);
    float* sD0 = (float*)(sm + SD0);
    int tid = threadIdx.x, w = tid >> 5, lane = tid & 31;
    const float* X = use_internal ? g_h : Xext;
    int nbase = blockIdx.x * 128;
    int ntail = n - nbase; if (ntail > 128) ntail = 128;

    // zero A smem only for the tail tile
    if (ntail < 128) {
        #pragma unroll
        for (int i = 0; i < 16; i++) {
            asm volatile("st.shared.v4.b32 [%0], {%1,%1,%1,%1};"
                         :: "r"(sb + SA_HI + (u32)(tid * 16 + i * 4096)), "r"(0u));
        }
    }
    __syncthreads();

    // ---- convert X tile to bf16 hi/lo, swizzled ----
    #pragma unroll
    for (int it = 0; it < 8; it++) {
        int idx = tid + it * 256;          // 2048 chunks
        int row = idx >> 4, c = idx & 15;
        if (row < ntail) {
            const float* xp = X + (size_t)(nbase + row) * 128 + c * 8;
            float4 v0 = *(const float4*)xp;
            float4 v1 = *(const float4*)(xp + 4);
            float f[8] = {v0.x, v0.y, v0.z, v0.w, v1.x, v1.y, v1.z, v1.w};
            u32 hp[4], lp[4];
            #pragma unroll
            for (int q = 0; q < 4; q++) {
                __nv_bfloat16 h0 = __float2bfloat16(f[2 * q]);
                __nv_bfloat16 h1 = __float2bfloat16(f[2 * q + 1]);
                __nv_bfloat16 l0 = __float2bfloat16(f[2 * q] - __bfloat162float(h0));
                __nv_bfloat16 l1 = __float2bfloat16(f[2 * q + 1] - __bfloat162float(h1));
                __nv_bfloat162 hh; hh.x = h0; hh.y = h1;
                __nv_bfloat162 ll; ll.x = l0; ll.y = l1;
                hp[q] = *(u32*)&hh;
                lp[q] = *(u32*)&ll;
            }
            asm volatile("st.shared.v4.b32 [%0], {%1,%2,%3,%4};"
                         :: "r"(sw_addr(sb + SA_HI, row, c)), "r"(hp[0]), "r"(hp[1]), "r"(hp[2]), "r"(hp[3]));
            asm volatile("st.shared.v4.b32 [%0], {%1,%2,%3,%4};"
                         :: "r"(sw_addr(sb + SA_LO, row, c)), "r"(lp[0]), "r"(lp[1]), "r"(lp[2]), "r"(lp[3]));
        }
    }

    const __nv_bfloat16* prep = &g_wprep[layer][0][0][0];
    int r0 = 16 * w + (lane >> 2);
    int c0 = 2 * (lane & 3);

    // ---- matrix 0 (W -> m), stash to smem fp32 ----
    {
        stage32k(sb + SB_HI, prep, tid);
        stage32k(sb + SB_LO, prep + 16384, tid);
        __syncthreads();
        float acc[16][4];
        #pragma unroll
        for (int i = 0; i < 16; i++) { acc[i][0] = acc[i][1] = acc[i][2] = acc[i][3] = 0.f; }
        gemm_mat(acc, sb + SA_HI, sb + SA_LO, sb + SB_HI, sb + SB_LO, w, lane);
        #pragma unroll
        for (int nt = 0; nt < 16; nt++) {
            *(float2*)&sD0[r0 * D0_PITCH + nt * 8 + c0] = make_float2(acc[nt][0], acc[nt][1]);
            *(float2*)&sD0[(r0 + 8) * D0_PITCH + nt * 8 + c0] = make_float2(acc[nt][2], acc[nt][3]);
        }
        __syncthreads();
    }

    // ---- matrix 1 (gamma) in regs ----
    float accG[16][4];
    {
        stage32k(sb + SB_HI, prep + 2 * 16384, tid);
        stage32k(sb + SB_LO, prep + 3 * 16384, tid);
        __syncthreads();
        #pragma unroll
        for (int i = 0; i < 16; i++) { accG[i][0] = accG[i][1] = accG[i][2] = accG[i][3] = 0.f; }
        gemm_mat(accG, sb + SA_HI, sb + SA_LO, sb + SB_HI, sb + SB_LO, w, lane);
        __syncthreads();
    }

    // ---- matrix 2 (beta) in regs ----
    float accB[16][4];
    {
        stage32k(sb + SB_HI, prep + 4 * 16384, tid);
        stage32k(sb + SB_LO, prep + 5 * 16384, tid);
        __syncthreads();
        #pragma unroll
        for (int i = 0; i < 16; i++) { accB[i][0] = accB[i][1] = accB[i][2] = accB[i][3] = 0.f; }
        gemm_mat(accB, sb + SA_HI, sb + SA_LO, sb + SB_HI, sb + SB_LO, w, lane);
    }

    // ---- epilogue: msg = relu(gamma*m + beta) ----
    bool okA = (r0 < ntail), okB = (r0 + 8 < ntail);
    float* outA = g_msg + (size_t)(nbase + r0) * 128;
    float* outB = g_msg + (size_t)(nbase + r0 + 8) * 128;
    #pragma unroll
    for (int nt = 0; nt < 16; nt++) {
        float2 mA = *(float2*)&sD0[r0 * D0_PITCH + nt * 8 + c0];
        float2 mB = *(float2*)&sD0[(r0 + 8) * D0_PITCH + nt * 8 + c0];
        if (okA) {
            float2 o;
            o.x = fmaxf(fmaf(accG[nt][0], mA.x, accB[nt][0]), 0.f);
            o.y = fmaxf(fmaf(accG[nt][1], mA.y, accB[nt][1]), 0.f);
            *(float2*)(outA + nt * 8 + c0) = o;
        }
        if (okB) {
            float2 o;
            o.x = fmaxf(fmaf(accG[nt][2], mB.x, accB[nt][2]), 0.f);
            o.y = fmaxf(fmaf(accG[nt][3], mB.y, accB[nt][3]), 0.f);
            *(float2*)(outB + nt * 8 + c0) = o;
        }
    }
}

// ===================== gather (segment sum) + layernorm =====================
// one warp per destination node; 4-way unrolled edge loop for MLP.

__global__ void __launch_bounds__(256)
k_gather_ln(const float* __restrict__ gw, const float* __restrict__ bw, int n) {
    int node = blockIdx.x * 8 + (threadIdx.x >> 5);
    int lane = threadIdx.x & 31;
    if (node >= n) return;
    int beg = g_rowptr[node], end = g_rowptr[node + 1];
    const float4* __restrict__ msg4 = (const float4*)g_msg;
    float4 a0 = make_float4(0.f, 0.f, 0.f, 0.f), a1 = a0, a2 = a0, a3 = a0;
    int i = beg;
    for (; i + 4 <= end; i += 4) {
        int s0 = g_srclist[i + 0], s1 = g_srclist[i + 1];
        int s2 = g_srclist[i + 2], s3 = g_srclist[i + 3];
        float4 v0 = __ldg(&msg4[(size_t)s0 * 32 + lane]);
        float4 v1 = __ldg(&msg4[(size_t)s1 * 32 + lane]);
        float4 v2 = __ldg(&msg4[(size_t)s2 * 32 + lane]);
        float4 v3 = __ldg(&msg4[(size_t)s3 * 32 + lane]);
        a0.x += v0.x; a0.y += v0.y; a0.z += v0.z; a0.w += v0.w;
        a1.x += v1.x; a1.y += v1.y; a1.z += v1.z; a1.w += v1.w;
        a2.x += v2.x; a2.y += v2.y; a2.z += v2.z; a2.w += v2.w;
        a3.x += v3.x; a3.y += v3.y; a3.z += v3.z; a3.w += v3.w;
    }
    for (; i < end; i++) {
        int s = g_srclist[i];
        float4 v = __ldg(&msg4[(size_t)s * 32 + lane]);
        a0.x += v.x; a0.y += v.y; a0.z += v.z; a0.w += v.w;
    }
    float4 a;
    a.x = (a0.x + a1.x) + (a2.x + a3.x);
    a.y = (a0.y + a1.y) + (a2.y + a3.y);
    a.z = (a0.z + a1.z) + (a2.z + a3.z);
    a.w = (a0.w + a1.w) + (a2.w + a3.w);
    float loc = a.x + a.y + a.z + a.w;
    #pragma unroll
    for (int o = 16; o; o >>= 1) loc += __shfl_xor_sync(0xffffffffu, loc, o);
    float mu = loc * (1.0f / 128.0f);
    float d0 = a.x - mu, d1 = a.y - mu, d2 = a.z - mu, d3 = a.w - mu;
    float l2 = d0 * d0 + d1 * d1 + d2 * d2 + d3 * d3;
    #pragma unroll
    for (int o = 16; o; o >>= 1) l2 += __shfl_xor_sync(0xffffffffu, l2, o);
    float rs = rsqrtf(l2 * (1.0f / 128.0f) + LN_EPS);
    float4 gg = __ldg(&((const float4*)gw)[lane]);
    float4 bb = __ldg(&((const float4*)bw)[lane]);
    float4 o4;
    o4.x = d0 * rs * gg.x + bb.x;
    o4.y = d1 * rs * gg.y + bb.y;
    o4.z = d2 * rs * gg.z + bb.z;
    o4.w = d3 * rs * gg.w + bb.w;
    ((float4*)g_h)[(size_t)node * 32 + lane] = o4;
}

// ===================== projection: sigmoid(h @ Wp.T + bp) =====================

#define SMEM_PROJ ((128 * 64 + 64 * 128) * 4)

__global__ void __launch_bounds__(256, 1)
k_proj(const float* __restrict__ Wp, const float* __restrict__ bp,
       float* __restrict__ out, int n) {
    extern __shared__ float smf[];
    float* sWp = smf;
    float* sX = smf + 128 * 64;
    int t = threadIdx.x;
    int nbase = blockIdx.x * 64;
    int nt = n - nbase; if (nt > 64) nt = 64;

    {
        int j = t & 63, seg = t >> 6;
        const float4* w4 = (const float4*)(Wp + (size_t)j * 128);
        #pragma unroll
        for (int kk = 0; kk < 8; kk++) {
            int q = seg * 8 + kk;
            float4 v = w4[q];
            int k = q * 4;
            sWp[(k + 0) * 64 + j] = v.x;
            sWp[(k + 1) * 64 + j] = v.y;
            sWp[(k + 2) * 64 + j] = v.z;
            sWp[(k + 3) * 64 + j] = v.w;
        }
    }
    {
        const float4* x4 = (const float4*)g_h;
        float4* sx4 = (float4*)sX;
        #pragma unroll
        for (int i = 0; i < 8; i++) {
            int idx = t + i * 256;
            int row = idx >> 5, q = idx & 31;
            float4 v = (row < nt) ? x4[(size_t)(nbase + row) * 32 + q]
                                  : make_float4(0.f, 0.f, 0.f, 0.f);
            sx4[row * 32 + q] = v;
        }
    }
    __syncthreads();

    int warp = t >> 5, lane = t & 31;
    int n0 = warp * 8;
    const float* sXb = sX + n0 * 128;
    ull acc[8];
    #pragma unroll
    for (int i = 0; i < 8; i++) acc[i] = 0ull;

    #pragma unroll 4
    for (int k = 0; k < 128; k++) {
        ull wv = *(const ull*)(sWp + k * 64 + 2 * lane);
        #pragma unroll
        for (int i = 0; i < 8; i++)
            acc[i] = ffma2(pack2(sXb[i * 128 + k]), wv, acc[i]);
    }

    float2 bv = ((const float2*)bp)[lane];
    #pragma unroll
    for (int i = 0; i < 8; i++) {
        if (n0 + i < nt) {
            float2 s = unpack2(acc[i]);
            float v0 = 1.0f / (1.0f + __expf(-(s.x + bv.x)));
            float v1 = 1.0f / (1.0f + __expf(-(s.y + bv.y)));
            *(float2*)(out + (size_t)(nbase + n0 + i) * 64 + 2 * lane) = make_float2(v0, v1);
        }
    }
}

// ============================ launch ============================

extern "C" void kernel_launch(void* const* d_in, const int* in_sizes, int n_in,
                              void* d_out, int out_size) {
    const float* feats = (const float*)d_in[0];
    const int*   src   = (const int*)d_in[1];
    const int*   dst   = (const int*)d_in[2];
    const float* W1    = (const float*)d_in[3];
    const float* F1    = (const float*)d_in[4];
    const float* g1    = (const float*)d_in[5];
    const float* b1    = (const float*)d_in[6];
    const float* W2    = (const float*)d_in[7];
    const float* F2    = (const float*)d_in[8];
    const float* g2    = (const float*)d_in[9];
    const float* b2    = (const float*)d_in[10];
    const float* Wp    = (const float*)d_in[11];
    const float* bp    = (const float*)d_in[12];
    float* out = (float*)d_out;

    int n = in_sizes[0] / 128;   // 50000
    int e = in_sizes[1];         // 600000

    cudaFuncSetAttribute(k_film_mma, cudaFuncAttributeMaxDynamicSharedMemorySize, SMEM_MMA);
    cudaFuncSetAttribute(k_proj, cudaFuncAttributeMaxDynamicSharedMemorySize, SMEM_PROJ);

    int mtiles = (n + 127) / 128;
    int ptiles = (n + 63) / 64;
    int nb = (n + 255) / 256;    // scan blocks (196)

    // Side stream + fork/join events. Created ONCE on the first (uncaptured)
    // correctness call; reused identically on the capture call so every call
    // performs the same deterministic GPU work. No device memory involved.
    static cudaStream_t s2 = nullptr;
    static cudaEvent_t evFork = nullptr, evJoin = nullptr;
    if (!s2) {
        cudaStreamCreateWithFlags(&s2, cudaStreamNonBlocking);
        cudaEventCreateWithFlags(&evFork, cudaEventDisableTiming);
        cudaEventCreateWithFlags(&evJoin, cudaEventDisableTiming);
    }

    // ---- fork: CSR build on side stream (independent of prep/film1) ----
    cudaEventRecord(evFork, 0);
    cudaStreamWaitEvent(s2, evFork, 0);
    k_zero<<<(n + 255) / 256, 256, 0, s2>>>(n);
    k_count<<<(e + 255) / 256, 256, 0, s2>>>(dst, e);
    k_scan_a<<<nb, 256, 0, s2>>>(n);
    k_scan_b<<<1, 256, 0, s2>>>(nb);
    k_scan_c<<<nb, 256, 0, s2>>>(n, e);
    k_fill<<<(e + 255) / 256, 256, 0, s2>>>(src, dst, e);
    cudaEventRecord(evJoin, s2);

    // ---- main stream: weight prep + layer-1 GEMM (overlaps CSR) ----
    k_prep<<<6, 256>>>(W1, F1, W2, F2);
    k_film_mma<<<mtiles, 256, SMEM_MMA>>>(feats, 0, 0, n);

    // ---- join: gather needs both msg (main) and CSR (side) ----
    cudaStreamWaitEvent(0, evJoin, 0);

    k_gather_ln<<<(n + 7) / 8, 256>>>(g1, b1, n);
    // layer 2
    k_film_mma<<<mtiles, 256, SMEM_MMA>>>(nullptr, 1, 1, n);
    k_gather_ln<<<(n + 7) / 8, 256>>>(g2, b2, n);
    // projection
    k_proj<<<ptiles, 256, SMEM_PROJ>>>(Wp, bp, out, n);
}